// round 10
// baseline (speedup 1.0000x reference)
#include <cuda_runtime.h>
#include <math.h>
#include <stdint.h>

#define NP 8732
#define NC 21
#define NB 128
#define NO 32
#define TPB 512
#define PPT 18           // ceil(8732/512)
#define THRESH 0.5f
#define ALPHA 10.0

// dynamic smem layout (bytes)
#define STAGE_BYTES (16 * 32 * NC * 4)          // 43008: per-warp CE staging
#define SCE_OFF     STAGE_BYTES                  // 34928: CE of negatives
#define SOV_OFF     (SCE_OFF + NP * 4)           //  8732: force-match obj per prior
#define DSM_BYTES   (SOV_OFF + NP + 4)

// per-block outputs (written every launch -> no init kernel needed)
__device__ double g_hard[NB];
__device__ double g_loc[NB];
__device__ double g_cp[NB];
__device__ int    g_np[NB];

__global__ __launch_bounds__(TPB, 1)
void fused_k(const float* __restrict__ pred_loc,
             const float* __restrict__ pred_cls,
             const float* __restrict__ b_boxes,
             const int*   __restrict__ b_labels,
             const float* __restrict__ priors) {
    const int b    = blockIdx.x;
    const int tid  = threadIdx.x;
    const int lane = tid & 31;
    const int wid  = tid >> 5;     // 0..15

    extern __shared__ char dsm[];
    float*         stage = (float*)dsm;                 // [16][672]
    float*         sce   = (float*)(dsm + SCE_OFF);     // [NP]
    unsigned char* sov   = (unsigned char*)(dsm + SOV_OFF);

    __shared__ float sbx1[NO], sby1[NO], sbx2[NO], sby2[NO], sba[NO];
    __shared__ int   slab[NO];
    __shared__ int   sbest[NO];
    __shared__ float swv[4][16];
    __shared__ int   swi[4][16];
    __shared__ int   sscnt[32];               // one counter per radix pass
    __shared__ int   snpos;
    __shared__ int    siw[16];
    __shared__ double sdw[16];
    __shared__ double sdw2[16];

    if (tid < NO) {
        const float* bb = b_boxes + ((size_t)b * NO + tid) * 4;
        float x1 = bb[0], y1 = bb[1], x2 = bb[2], y2 = bb[3];
        sbx1[tid] = x1; sby1[tid] = y1; sbx2[tid] = x2; sby2[tid] = y2;
        sba[tid]  = (x2 - x1) * (y2 - y1);
        slab[tid] = b_labels[b * NO + tid];
    }
    if (tid < 32) sscnt[tid] = 0;
    #pragma unroll
    for (int i = 0; i < PPT; i++) {
        int p = tid + i * TPB;
        if (p < NP) sov[p] = 255;
    }
    __syncthreads();

    // ---------------- Phase A: single IoU pass ----------------
    float pbv[PPT]; int pbm[PPT];
    #pragma unroll
    for (int i = 0; i < PPT; i++) { pbv[i] = -1.0f; pbm[i] = 0; }

    for (int g = 0; g < NO / 4; ++g) {
        float B1[4], B2[4], B3[4], B4[4], BA[4];
        #pragma unroll
        for (int j = 0; j < 4; j++) {
            int m = g * 4 + j;
            B1[j] = sbx1[m]; B2[j] = sby1[m];
            B3[j] = sbx2[m]; B4[j] = sby2[m]; BA[j] = sba[m];
        }
        float obv[4]; int obi[4];
        #pragma unroll
        for (int j = 0; j < 4; j++) { obv[j] = -1.0f; obi[j] = 0x7fffffff; }

        #pragma unroll
        for (int i = 0; i < PPT; i++) {
            int p = tid + i * TPB;
            if (p < NP) {
                float4 pc = reinterpret_cast<const float4*>(priors)[p];
                float hw  = pc.z * 0.5f, hh = pc.w * 0.5f;
                float px1 = pc.x - hw, py1 = pc.y - hh;
                float px2 = pc.x + hw, py2 = pc.y + hh;
                float pa  = (px2 - px1) * (py2 - py1);
                #pragma unroll
                for (int j = 0; j < 4; j++) {
                    float ix1 = fmaxf(B1[j], px1), iy1 = fmaxf(B2[j], py1);
                    float ix2 = fminf(B3[j], px2), iy2 = fminf(B4[j], py2);
                    float iw  = fmaxf(ix2 - ix1, 0.0f);
                    float ih  = fmaxf(iy2 - iy1, 0.0f);
                    float inter = iw * ih;
                    float uni   = (BA[j] + pa) - inter;
                    float iou   = __fdividef(inter, uni);     // rcp+mul
                    if (iou > pbv[i]) { pbv[i] = iou; pbm[i] = g * 4 + j; }
                    if (iou > obv[j]) { obv[j] = iou; obi[j] = p; }
                }
            }
        }
        // block argmax for the 4 objects of this group (min index on ties)
        #pragma unroll
        for (int j = 0; j < 4; j++) {
            float v = obv[j]; int ix = obi[j];
            #pragma unroll
            for (int o = 16; o > 0; o >>= 1) {
                float v2 = __shfl_down_sync(0xffffffffu, v, o);
                int   i2 = __shfl_down_sync(0xffffffffu, ix, o);
                if (v2 > v || (v2 == v && i2 < ix)) { v = v2; ix = i2; }
            }
            if (lane == 0) { swv[j][wid] = v; swi[j][wid] = ix; }
        }
        __syncthreads();
        if (wid < 4 && lane < 16) {
            float v = swv[wid][lane]; int ix = swi[wid][lane];
            #pragma unroll
            for (int o = 8; o > 0; o >>= 1) {
                float v2 = __shfl_down_sync(0xffffu, v, o);
                int   i2 = __shfl_down_sync(0xffffu, ix, o);
                if (v2 > v || (v2 == v && i2 < ix)) { v = v2; ix = i2; }
            }
            if (lane == 0) sbest[g * 4 + wid] = ix;
        }
        __syncthreads();
    }

    // min object per overridden prior (descending m -> smallest m wins)
    if (tid == 0) {
        for (int m = NO - 1; m >= 0; --m) sov[sbest[m]] = (unsigned char)m;
    }
    __syncthreads();

    // ---------------- Phase B: coalesced CE via warp staging + loc -------
    int    npl  = 0;
    double cpl  = 0.0;
    double locl = 0.0;
    float* st = stage + wid * (32 * NC);   // this warp's 672-float buffer

    #pragma unroll
    for (int i = 0; i < PPT; i++) {
        int p0 = i * TPB + wid * 32;       // first prior of this warp this iter
        int p  = p0 + lane;                // == tid + i*TPB  (same as Phase A)

        if (p0 < NP) {
            const float* span = pred_cls + ((size_t)b * NP + p0) * NC;
            if (p0 + 32 <= NP) {
                // fully in-range: 168 coalesced float4 loads
                const float4* s4 = (const float4*)span;
                float4*       d4 = (float4*)st;
                for (int f = lane; f < (32 * NC) / 4; f += 32) d4[f] = s4[f];
            } else {
                for (int e = lane; e < 32 * NC; e += 32) {
                    int pp = p0 + e / NC;
                    st[e] = (pp < NP) ? span[e] : 0.0f;
                }
            }
        }
        __syncwarp();

        if (p < NP) {
            float bv = pbv[i]; int bm = pbm[i];
            int ov = sov[p];
            if (ov != 255) {
                if (bv < 1.0f || (bv == 1.0f && ov < bm)) { bv = 1.0f; bm = ov; }
            }
            bool pos = (bv >= THRESH);
            int  cls = pos ? slab[bm] : 0;

            const float* row = st + lane * NC;   // stride 21 words: conflict-free
            float se = 0.0f;
            #pragma unroll
            for (int c = 0; c < NC; c++) se += __expf(row[c]);
            float ce = __logf(se) - row[cls];

            if (pos) {
                sce[p] = 0.0f;
                npl++;
                cpl += (double)ce;
                float4 pc = reinterpret_cast<const float4*>(priors)[p];
                float x1 = sbx1[bm], y1 = sby1[bm], x2 = sbx2[bm], y2 = sby2[bm];
                float cx = (x1 + x2) * 0.5f, cy = (y1 + y2) * 0.5f;
                float bw = x2 - x1, bh = y2 - y1;
                float gx = (cx - pc.x) / (pc.z / 10.0f);
                float gy = (cy - pc.y) / (pc.w / 10.0f);
                float gw = __logf(bw / pc.z) * 5.0f;
                float gh = __logf(bh / pc.w) * 5.0f;
                float4 pl = reinterpret_cast<const float4*>(pred_loc)[(size_t)b * NP + p];
                locl += (double)(fabsf(pl.x - gx) + fabsf(pl.y - gy) +
                                 fabsf(pl.z - gw) + fabsf(pl.w - gh));
            } else {
                sce[p] = fmaxf(ce, 0.0f);   // guard tiny negatives
            }
        }
        __syncwarp();   // protect stage before next iteration overwrites
    }

    // block reduce npos / conf_pos / loc
    #pragma unroll
    for (int o = 16; o > 0; o >>= 1) {
        npl  += __shfl_down_sync(0xffffffffu, npl, o);
        cpl  += __shfl_down_sync(0xffffffffu, cpl, o);
        locl += __shfl_down_sync(0xffffffffu, locl, o);
    }
    if (lane == 0) { siw[wid] = npl; sdw[wid] = cpl; sdw2[wid] = locl; }
    __syncthreads();
    if (wid == 0 && lane < 16) {
        int n = siw[lane]; double c = sdw[lane]; double l = sdw2[lane];
        #pragma unroll
        for (int o = 8; o > 0; o >>= 1) {
            n += __shfl_down_sync(0xffffu, n, o);
            c += __shfl_down_sync(0xffffu, c, o);
            l += __shfl_down_sync(0xffffu, l, o);
        }
        if (lane == 0) { snpos = n; g_np[b] = n; g_cp[b] = c; g_loc[b] = l; }
    }
    __syncthreads();

    // ---------------- Phase C: exact top-K via radix select on smem ------
    int K = 3 * snpos;
    if (K > NP) K = NP;

    unsigned t = 0u;
    for (int bit = 30; bit >= 0; --bit) {
        unsigned cand = t | (1u << bit);
        int c = 0;
        #pragma unroll
        for (int i = 0; i < PPT; i++) {
            int p = tid + i * TPB;
            if (p < NP && __float_as_uint(sce[p]) >= cand) c++;
        }
        #pragma unroll
        for (int o = 16; o > 0; o >>= 1) c += __shfl_down_sync(0xffffffffu, c, o);
        if (lane == 0 && c) atomicAdd(&sscnt[bit], c);
        __syncthreads();
        if (sscnt[bit] >= K) t = cand;
        // next pass uses a different counter slot -> no second sync needed
    }

    int    cgt = 0;
    double sg  = 0.0;
    #pragma unroll
    for (int i = 0; i < PPT; i++) {
        int p = tid + i * TPB;
        if (p < NP) {
            unsigned v = __float_as_uint(sce[p]);
            if (v > t) { cgt++; sg += (double)__uint_as_float(v); }
        }
    }
    #pragma unroll
    for (int o = 16; o > 0; o >>= 1) {
        cgt += __shfl_down_sync(0xffffffffu, cgt, o);
        sg  += __shfl_down_sync(0xffffffffu, sg, o);
    }
    __syncthreads();            // safe reuse of siw/sdw
    if (lane == 0) { siw[wid] = cgt; sdw[wid] = sg; }
    __syncthreads();
    if (tid == 0) {
        int c = 0; double sm = 0.0;
        #pragma unroll
        for (int w = 0; w < 16; w++) { c += siw[w]; sm += sdw[w]; }
        g_hard[b] = sm + (double)(K - c) * (double)__uint_as_float(t);
    }
}

// ---------------- finalize: reduce 128 per-image slots ----------------
__global__ void finalize_k(float* __restrict__ out) {
    int tid  = threadIdx.x;           // 128 threads
    int lane = tid & 31, wid = tid >> 5;
    double h = g_hard[tid] + g_cp[tid];
    double l = g_loc[tid];
    int    n = g_np[tid];
    #pragma unroll
    for (int o = 16; o > 0; o >>= 1) {
        h += __shfl_down_sync(0xffffffffu, h, o);
        l += __shfl_down_sync(0xffffffffu, l, o);
        n += __shfl_down_sync(0xffffffffu, n, o);
    }
    __shared__ double sh[4], sl[4];
    __shared__ int    sn[4];
    if (lane == 0) { sh[wid] = h; sl[wid] = l; sn[wid] = n; }
    __syncthreads();
    if (tid == 0) {
        double H = sh[0] + sh[1] + sh[2] + sh[3];
        double L = sl[0] + sl[1] + sl[2] + sl[3];
        double N = (double)(sn[0] + sn[1] + sn[2] + sn[3]);
        double loc  = ALPHA * (L / (N * 4.0));
        double conf = H / N;
        out[0] = (float)(conf + loc);
        out[1] = (float)loc;
        out[2] = (float)conf;
    }
}

extern "C" void kernel_launch(void* const* d_in, const int* in_sizes, int n_in,
                              void* d_out, int out_size) {
    const float* pred_loc = (const float*)d_in[0];
    const float* pred_cls = (const float*)d_in[1];
    const float* b_boxes  = (const float*)d_in[2];
    const int*   b_labels = (const int*)  d_in[3];
    const float* priors   = (const float*)d_in[4];
    float* out = (float*)d_out;

    cudaFuncSetAttribute(fused_k, cudaFuncAttributeMaxDynamicSharedMemorySize,
                         DSM_BYTES);
    fused_k<<<NB, TPB, DSM_BYTES>>>(pred_loc, pred_cls, b_boxes, b_labels, priors);
    finalize_k<<<1, NB>>>(out);
}

// round 11
// speedup vs baseline: 1.0089x; 1.0089x over previous
#include <cuda_runtime.h>
#include <math.h>
#include <stdint.h>

#define NP 8732
#define NC 21
#define NB 128
#define NO 32
#define TPB 512
#define PPT 18           // ceil(8732/512)
#define THRESH 0.5f
#define ALPHA 10.0

// dynamic smem layout (bytes)
#define STAGE_BYTES (16 * 32 * NC * 4)          // 43008: per-warp CE staging
#define SCE_OFF     STAGE_BYTES                  // 34928: CE of negatives
#define SOV_OFF     (SCE_OFF + NP * 4)           //  8732: force-match obj per prior
#define DSM_BYTES   (SOV_OFF + NP + 4)

// per-block outputs (written every launch -> no init kernel needed)
__device__ double g_hard[NB];
__device__ double g_loc[NB];
__device__ double g_cp[NB];
__device__ int    g_np[NB];

__global__ __launch_bounds__(TPB, 1)
void fused_k(const float* __restrict__ pred_loc,
             const float* __restrict__ pred_cls,
             const float* __restrict__ b_boxes,
             const int*   __restrict__ b_labels,
             const float* __restrict__ priors) {
    const int b    = blockIdx.x;
    const int tid  = threadIdx.x;
    const int lane = tid & 31;
    const int wid  = tid >> 5;     // 0..15

    extern __shared__ char dsm[];
    float*         stage = (float*)dsm;                 // [16][672]
    float*         sce   = (float*)(dsm + SCE_OFF);     // [NP]
    unsigned char* sov   = (unsigned char*)(dsm + SOV_OFF);

    __shared__ float sbx1[NO], sby1[NO], sbx2[NO], sby2[NO], sba[NO];
    __shared__ int   slab[NO];
    __shared__ int   sbest[NO];
    __shared__ float swv[4][16];
    __shared__ int   swi[4][16];
    __shared__ int   sscnt[32];               // one counter per radix pass
    __shared__ int   snpos;
    __shared__ int    siw[16];
    __shared__ double sdw[16];
    __shared__ double sdw2[16];

    if (tid < NO) {
        const float* bb = b_boxes + ((size_t)b * NO + tid) * 4;
        float x1 = bb[0], y1 = bb[1], x2 = bb[2], y2 = bb[3];
        sbx1[tid] = x1; sby1[tid] = y1; sbx2[tid] = x2; sby2[tid] = y2;
        sba[tid]  = (x2 - x1) * (y2 - y1);
        slab[tid] = b_labels[b * NO + tid];
    }
    if (tid < 32) sscnt[tid] = 0;
    #pragma unroll
    for (int i = 0; i < PPT; i++) {
        int p = tid + i * TPB;
        if (p < NP) sov[p] = 255;
    }
    __syncthreads();

    // ---------------- Phase A: single IoU pass ----------------
    float pbv[PPT]; int pbm[PPT];
    #pragma unroll
    for (int i = 0; i < PPT; i++) { pbv[i] = -1.0f; pbm[i] = 0; }

    for (int g = 0; g < NO / 4; ++g) {
        float B1[4], B2[4], B3[4], B4[4], BA[4];
        #pragma unroll
        for (int j = 0; j < 4; j++) {
            int m = g * 4 + j;
            B1[j] = sbx1[m]; B2[j] = sby1[m];
            B3[j] = sbx2[m]; B4[j] = sby2[m]; BA[j] = sba[m];
        }
        float obv[4]; int obi[4];
        #pragma unroll
        for (int j = 0; j < 4; j++) { obv[j] = -1.0f; obi[j] = 0x7fffffff; }

        #pragma unroll
        for (int i = 0; i < PPT; i++) {
            int p = tid + i * TPB;
            if (p < NP) {
                float4 pc = reinterpret_cast<const float4*>(priors)[p];
                float hw  = pc.z * 0.5f, hh = pc.w * 0.5f;
                float px1 = pc.x - hw, py1 = pc.y - hh;
                float px2 = pc.x + hw, py2 = pc.y + hh;
                float pa  = (px2 - px1) * (py2 - py1);
                #pragma unroll
                for (int j = 0; j < 4; j++) {
                    float ix1 = fmaxf(B1[j], px1), iy1 = fmaxf(B2[j], py1);
                    float ix2 = fminf(B3[j], px2), iy2 = fminf(B4[j], py2);
                    float iw  = fmaxf(ix2 - ix1, 0.0f);
                    float ih  = fmaxf(iy2 - iy1, 0.0f);
                    float inter = iw * ih;
                    float uni   = (BA[j] + pa) - inter;
                    float iou   = __fdividef(inter, uni);     // rcp+mul
                    if (iou > pbv[i]) { pbv[i] = iou; pbm[i] = g * 4 + j; }
                    if (iou > obv[j]) { obv[j] = iou; obi[j] = p; }
                }
            }
        }
        // block argmax for the 4 objects of this group (min index on ties)
        #pragma unroll
        for (int j = 0; j < 4; j++) {
            float v = obv[j]; int ix = obi[j];
            #pragma unroll
            for (int o = 16; o > 0; o >>= 1) {
                float v2 = __shfl_down_sync(0xffffffffu, v, o);
                int   i2 = __shfl_down_sync(0xffffffffu, ix, o);
                if (v2 > v || (v2 == v && i2 < ix)) { v = v2; ix = i2; }
            }
            if (lane == 0) { swv[j][wid] = v; swi[j][wid] = ix; }
        }
        __syncthreads();
        if (wid < 4 && lane < 16) {
            float v = swv[wid][lane]; int ix = swi[wid][lane];
            #pragma unroll
            for (int o = 8; o > 0; o >>= 1) {
                float v2 = __shfl_down_sync(0xffffu, v, o);
                int   i2 = __shfl_down_sync(0xffffu, ix, o);
                if (v2 > v || (v2 == v && i2 < ix)) { v = v2; ix = i2; }
            }
            if (lane == 0) sbest[g * 4 + wid] = ix;
        }
        __syncthreads();
    }

    // min object per overridden prior (descending m -> smallest m wins)
    if (tid == 0) {
        for (int m = NO - 1; m >= 0; --m) sov[sbest[m]] = (unsigned char)m;
    }
    __syncthreads();

    // ---------------- Phase B: coalesced CE via warp staging + loc -------
    int    npl  = 0;
    double cpl  = 0.0;
    double locl = 0.0;
    float* st = stage + wid * (32 * NC);   // this warp's 672-float buffer

    #pragma unroll
    for (int i = 0; i < PPT; i++) {
        int p0 = i * TPB + wid * 32;       // first prior of this warp this iter
        int p  = p0 + lane;                // == tid + i*TPB  (same as Phase A)

        if (p0 < NP) {
            const float* span = pred_cls + ((size_t)b * NP + p0) * NC;
            if (p0 + 32 <= NP) {
                // fully in-range: 168 coalesced float4 loads
                const float4* s4 = (const float4*)span;
                float4*       d4 = (float4*)st;
                for (int f = lane; f < (32 * NC) / 4; f += 32) d4[f] = s4[f];
            } else {
                for (int e = lane; e < 32 * NC; e += 32) {
                    int pp = p0 + e / NC;
                    st[e] = (pp < NP) ? span[e] : 0.0f;
                }
            }
        }
        __syncwarp();

        if (p < NP) {
            float bv = pbv[i]; int bm = pbm[i];
            int ov = sov[p];
            if (ov != 255) {
                if (bv < 1.0f || (bv == 1.0f && ov < bm)) { bv = 1.0f; bm = ov; }
            }
            bool pos = (bv >= THRESH);
            int  cls = pos ? slab[bm] : 0;

            const float* row = st + lane * NC;   // stride 21 words: conflict-free
            float se = 0.0f;
            #pragma unroll
            for (int c = 0; c < NC; c++) se += __expf(row[c]);
            float ce = __logf(se) - row[cls];

            if (pos) {
                sce[p] = 0.0f;
                npl++;
                cpl += (double)ce;
                float4 pc = reinterpret_cast<const float4*>(priors)[p];
                float x1 = sbx1[bm], y1 = sby1[bm], x2 = sbx2[bm], y2 = sby2[bm];
                float cx = (x1 + x2) * 0.5f, cy = (y1 + y2) * 0.5f;
                float bw = x2 - x1, bh = y2 - y1;
                float gx = (cx - pc.x) / (pc.z / 10.0f);
                float gy = (cy - pc.y) / (pc.w / 10.0f);
                float gw = __logf(bw / pc.z) * 5.0f;
                float gh = __logf(bh / pc.w) * 5.0f;
                float4 pl = reinterpret_cast<const float4*>(pred_loc)[(size_t)b * NP + p];
                locl += (double)(fabsf(pl.x - gx) + fabsf(pl.y - gy) +
                                 fabsf(pl.z - gw) + fabsf(pl.w - gh));
            } else {
                sce[p] = fmaxf(ce, 0.0f);   // guard tiny negatives
            }
        }
        __syncwarp();   // protect stage before next iteration overwrites
    }

    // block reduce npos / conf_pos / loc
    #pragma unroll
    for (int o = 16; o > 0; o >>= 1) {
        npl  += __shfl_down_sync(0xffffffffu, npl, o);
        cpl  += __shfl_down_sync(0xffffffffu, cpl, o);
        locl += __shfl_down_sync(0xffffffffu, locl, o);
    }
    if (lane == 0) { siw[wid] = npl; sdw[wid] = cpl; sdw2[wid] = locl; }
    __syncthreads();
    if (wid == 0 && lane < 16) {
        int n = siw[lane]; double c = sdw[lane]; double l = sdw2[lane];
        #pragma unroll
        for (int o = 8; o > 0; o >>= 1) {
            n += __shfl_down_sync(0xffffu, n, o);
            c += __shfl_down_sync(0xffffu, c, o);
            l += __shfl_down_sync(0xffffu, l, o);
        }
        if (lane == 0) { snpos = n; g_np[b] = n; g_cp[b] = c; g_loc[b] = l; }
    }
    __syncthreads();

    // ---------------- Phase C: exact top-K via radix select on smem ------
    int K = 3 * snpos;
    if (K > NP) K = NP;

    unsigned t = 0u;
    for (int bit = 30; bit >= 0; --bit) {
        unsigned cand = t | (1u << bit);
        int c = 0;
        #pragma unroll
        for (int i = 0; i < PPT; i++) {
            int p = tid + i * TPB;
            if (p < NP && __float_as_uint(sce[p]) >= cand) c++;
        }
        #pragma unroll
        for (int o = 16; o > 0; o >>= 1) c += __shfl_down_sync(0xffffffffu, c, o);
        if (lane == 0 && c) atomicAdd(&sscnt[bit], c);
        __syncthreads();
        if (sscnt[bit] >= K) t = cand;
        // next pass uses a different counter slot -> no second sync needed
    }

    int    cgt = 0;
    double sg  = 0.0;
    #pragma unroll
    for (int i = 0; i < PPT; i++) {
        int p = tid + i * TPB;
        if (p < NP) {
            unsigned v = __float_as_uint(sce[p]);
            if (v > t) { cgt++; sg += (double)__uint_as_float(v); }
        }
    }
    #pragma unroll
    for (int o = 16; o > 0; o >>= 1) {
        cgt += __shfl_down_sync(0xffffffffu, cgt, o);
        sg  += __shfl_down_sync(0xffffffffu, sg, o);
    }
    __syncthreads();            // safe reuse of siw/sdw
    if (lane == 0) { siw[wid] = cgt; sdw[wid] = sg; }
    __syncthreads();
    if (tid == 0) {
        int c = 0; double sm = 0.0;
        #pragma unroll
        for (int w = 0; w < 16; w++) { c += siw[w]; sm += sdw[w]; }
        g_hard[b] = sm + (double)(K - c) * (double)__uint_as_float(t);
    }
}

// ---------------- finalize: reduce 128 per-image slots ----------------
__global__ void finalize_k(float* __restrict__ out) {
    int tid  = threadIdx.x;           // 128 threads
    int lane = tid & 31, wid = tid >> 5;
    double h = g_hard[tid] + g_cp[tid];
    double l = g_loc[tid];
    int    n = g_np[tid];
    #pragma unroll
    for (int o = 16; o > 0; o >>= 1) {
        h += __shfl_down_sync(0xffffffffu, h, o);
        l += __shfl_down_sync(0xffffffffu, l, o);
        n += __shfl_down_sync(0xffffffffu, n, o);
    }
    __shared__ double sh[4], sl[4];
    __shared__ int    sn[4];
    if (lane == 0) { sh[wid] = h; sl[wid] = l; sn[wid] = n; }
    __syncthreads();
    if (tid == 0) {
        double H = sh[0] + sh[1] + sh[2] + sh[3];
        double L = sl[0] + sl[1] + sl[2] + sl[3];
        double N = (double)(sn[0] + sn[1] + sn[2] + sn[3]);
        double loc  = ALPHA * (L / (N * 4.0));
        double conf = H / N;
        out[0] = (float)(conf + loc);
        out[1] = (float)loc;
        out[2] = (float)conf;
    }
}

extern "C" void kernel_launch(void* const* d_in, const int* in_sizes, int n_in,
                              void* d_out, int out_size) {
    const float* pred_loc = (const float*)d_in[0];
    const float* pred_cls = (const float*)d_in[1];
    const float* b_boxes  = (const float*)d_in[2];
    const int*   b_labels = (const int*)  d_in[3];
    const float* priors   = (const float*)d_in[4];
    float* out = (float*)d_out;

    cudaFuncSetAttribute(fused_k, cudaFuncAttributeMaxDynamicSharedMemorySize,
                         DSM_BYTES);
    fused_k<<<NB, TPB, DSM_BYTES>>>(pred_loc, pred_cls, b_boxes, b_labels, priors);
    finalize_k<<<1, NB>>>(out);
}

// round 12
// speedup vs baseline: 1.3322x; 1.3204x over previous
#include <cuda_runtime.h>
#include <math.h>
#include <stdint.h>

#define NP 8732
#define NC 21
#define NB 128
#define NO 32
#define TPB 512
#define NG 2183          // NP/4 prior-groups (exact: 8732 = 4*2183)
#define GPT 5            // ceil(2183/512)
#define THRESH 0.5f
#define ALPHA 10.0

// dynamic smem layout (bytes)
#define SCE_OFF 0
#define SOV_OFF (NP * 4)                 // 34928
#define DSM_BYTES (SOV_OFF + NP + 16)    // ~43.7 KB

// per-block outputs (written every launch -> no init kernel needed)
__device__ double g_hard[NB];
__device__ double g_loc[NB];
__device__ double g_cp[NB];
__device__ int    g_np[NB];

__global__ __launch_bounds__(TPB, 1)
void fused_k(const float* __restrict__ pred_loc,
             const float* __restrict__ pred_cls,
             const float* __restrict__ b_boxes,
             const int*   __restrict__ b_labels,
             const float* __restrict__ priors) {
    const int b    = blockIdx.x;
    const int tid  = threadIdx.x;
    const int lane = tid & 31;
    const int wid  = tid >> 5;     // 0..15

    extern __shared__ char dsm[];
    float*         sce = (float*)(dsm + SCE_OFF);   // [NP] CE of negatives
    unsigned char* sov = (unsigned char*)(dsm + SOV_OFF);

    __shared__ float sbx1[NO], sby1[NO], sbx2[NO], sby2[NO], sba[NO];
    __shared__ int   slab[NO];
    __shared__ int   sbest[NO];
    __shared__ float swv[4][16];
    __shared__ int   swi[4][16];
    __shared__ int   sscnt[32];               // one counter per radix pass
    __shared__ int   snpos;
    __shared__ int    siw[16];
    __shared__ double sdw[16];
    __shared__ double sdw2[16];

    if (tid < NO) {
        const float* bb = b_boxes + ((size_t)b * NO + tid) * 4;
        float x1 = bb[0], y1 = bb[1], x2 = bb[2], y2 = bb[3];
        sbx1[tid] = x1; sby1[tid] = y1; sbx2[tid] = x2; sby2[tid] = y2;
        sba[tid]  = (x2 - x1) * (y2 - y1);
        slab[tid] = b_labels[b * NO + tid];
    }
    if (tid < 32) sscnt[tid] = 0;
    for (int p = tid; p < NP; p += TPB) sov[p] = 255;
    __syncthreads();

    // ---------------- Phase A: single IoU pass ----------------
    // thread owns priors 4*grp..4*grp+3 for grp = tid + i*TPB
    float pbv[GPT * 4]; int pbm[GPT * 4];
    #pragma unroll
    for (int i = 0; i < GPT * 4; i++) { pbv[i] = -1.0f; pbm[i] = 0; }

    for (int g = 0; g < NO / 4; ++g) {
        float B1[4], B2[4], B3[4], B4[4], BA[4];
        #pragma unroll
        for (int j = 0; j < 4; j++) {
            int m = g * 4 + j;
            B1[j] = sbx1[m]; B2[j] = sby1[m];
            B3[j] = sbx2[m]; B4[j] = sby2[m]; BA[j] = sba[m];
        }
        float obv[4]; int obi[4];
        #pragma unroll
        for (int j = 0; j < 4; j++) { obv[j] = -1.0f; obi[j] = 0x7fffffff; }

        #pragma unroll
        for (int i = 0; i < GPT; i++) {
            int grp = tid + i * TPB;
            if (grp < NG) {
                #pragma unroll
                for (int j = 0; j < 4; j++) {
                    int p = grp * 4 + j;
                    float4 pc = reinterpret_cast<const float4*>(priors)[p];
                    float hw  = pc.z * 0.5f, hh = pc.w * 0.5f;
                    float px1 = pc.x - hw, py1 = pc.y - hh;
                    float px2 = pc.x + hw, py2 = pc.y + hh;
                    float pa  = (px2 - px1) * (py2 - py1);
                    #pragma unroll
                    for (int jj = 0; jj < 4; jj++) {
                        float ix1 = fmaxf(B1[jj], px1), iy1 = fmaxf(B2[jj], py1);
                        float ix2 = fminf(B3[jj], px2), iy2 = fminf(B4[jj], py2);
                        float iw  = fmaxf(ix2 - ix1, 0.0f);
                        float ih  = fmaxf(iy2 - iy1, 0.0f);
                        float inter = iw * ih;
                        float uni   = (BA[jj] + pa) - inter;
                        float iou   = __fdividef(inter, uni);
                        if (iou > pbv[i * 4 + j]) { pbv[i * 4 + j] = iou; pbm[i * 4 + j] = g * 4 + jj; }
                        if (iou > obv[jj]) { obv[jj] = iou; obi[jj] = p; }
                    }
                }
            }
        }
        // block argmax for the 4 objects of this group (min index on ties)
        #pragma unroll
        for (int j = 0; j < 4; j++) {
            float v = obv[j]; int ix = obi[j];
            #pragma unroll
            for (int o = 16; o > 0; o >>= 1) {
                float v2 = __shfl_down_sync(0xffffffffu, v, o);
                int   i2 = __shfl_down_sync(0xffffffffu, ix, o);
                if (v2 > v || (v2 == v && i2 < ix)) { v = v2; ix = i2; }
            }
            if (lane == 0) { swv[j][wid] = v; swi[j][wid] = ix; }
        }
        __syncthreads();
        if (wid < 4 && lane < 16) {
            float v = swv[wid][lane]; int ix = swi[wid][lane];
            #pragma unroll
            for (int o = 8; o > 0; o >>= 1) {
                float v2 = __shfl_down_sync(0xffffu, v, o);
                int   i2 = __shfl_down_sync(0xffffu, ix, o);
                if (v2 > v || (v2 == v && i2 < ix)) { v = v2; ix = i2; }
            }
            if (lane == 0) sbest[g * 4 + wid] = ix;
        }
        __syncthreads();
    }

    // min object per overridden prior (descending m -> smallest m wins)
    if (tid == 0) {
        for (int m = NO - 1; m >= 0; --m) sov[sbest[m]] = (unsigned char)m;
    }
    __syncthreads();

    // ---------------- Phase B: CE via per-thread float4 rows + loc -------
    int    npl  = 0;
    double cpl  = 0.0;
    double locl = 0.0;

    #pragma unroll
    for (int i = 0; i < GPT; i++) {
        int grp = tid + i * TPB;
        if (grp < NG) {
            // matching fix-up for the 4 priors of this group
            int  cls[4]; bool pos[4]; int bm[4];
            #pragma unroll
            for (int j = 0; j < 4; j++) {
                int p = grp * 4 + j;
                float bv = pbv[i * 4 + j]; int m = pbm[i * 4 + j];
                int ov = sov[p];
                if (ov != 255) {
                    if (bv < 1.0f || (bv == 1.0f && ov < m)) { bv = 1.0f; m = ov; }
                }
                pos[j] = (bv >= THRESH);
                bm[j]  = m;
                cls[j] = pos[j] ? slab[m] : 0;
            }

            // stream 21 float4 (16B-aligned, 336B stride between threads)
            const float4* base = reinterpret_cast<const float4*>(
                pred_cls + ((size_t)b * NP + (size_t)grp * 4) * NC);
            float se[4] = {0.f, 0.f, 0.f, 0.f};
            float lc[4] = {0.f, 0.f, 0.f, 0.f};
            #pragma unroll
            for (int k = 0; k < NC; k++) {        // 21 float4 = 84 elements
                float4 v = base[k];
                {   int e = 4 * k + 0, r = e / NC, c = e % NC;
                    se[r] += __expf(v.x); if (c == cls[r]) lc[r] = v.x; }
                {   int e = 4 * k + 1, r = e / NC, c = e % NC;
                    se[r] += __expf(v.y); if (c == cls[r]) lc[r] = v.y; }
                {   int e = 4 * k + 2, r = e / NC, c = e % NC;
                    se[r] += __expf(v.z); if (c == cls[r]) lc[r] = v.z; }
                {   int e = 4 * k + 3, r = e / NC, c = e % NC;
                    se[r] += __expf(v.w); if (c == cls[r]) lc[r] = v.w; }
            }

            #pragma unroll
            for (int j = 0; j < 4; j++) {
                int p = grp * 4 + j;
                float ce = __logf(se[j]) - lc[j];
                if (pos[j]) {
                    sce[p] = 0.0f;
                    npl++;
                    cpl += (double)ce;
                    float4 pc = reinterpret_cast<const float4*>(priors)[p];
                    int m = bm[j];
                    float x1 = sbx1[m], y1 = sby1[m], x2 = sbx2[m], y2 = sby2[m];
                    float cx = (x1 + x2) * 0.5f, cy = (y1 + y2) * 0.5f;
                    float bw = x2 - x1, bh = y2 - y1;
                    float gx = (cx - pc.x) / (pc.z / 10.0f);
                    float gy = (cy - pc.y) / (pc.w / 10.0f);
                    float gw = __logf(bw / pc.z) * 5.0f;
                    float gh = __logf(bh / pc.w) * 5.0f;
                    float4 pl = reinterpret_cast<const float4*>(pred_loc)[(size_t)b * NP + p];
                    locl += (double)(fabsf(pl.x - gx) + fabsf(pl.y - gy) +
                                     fabsf(pl.z - gw) + fabsf(pl.w - gh));
                } else {
                    sce[p] = fmaxf(ce, 0.0f);   // guard tiny negatives
                }
            }
        }
    }

    // block reduce npos / conf_pos / loc
    #pragma unroll
    for (int o = 16; o > 0; o >>= 1) {
        npl  += __shfl_down_sync(0xffffffffu, npl, o);
        cpl  += __shfl_down_sync(0xffffffffu, cpl, o);
        locl += __shfl_down_sync(0xffffffffu, locl, o);
    }
    if (lane == 0) { siw[wid] = npl; sdw[wid] = cpl; sdw2[wid] = locl; }
    __syncthreads();
    if (wid == 0 && lane < 16) {
        int n = siw[lane]; double c = sdw[lane]; double l = sdw2[lane];
        #pragma unroll
        for (int o = 8; o > 0; o >>= 1) {
            n += __shfl_down_sync(0xffffu, n, o);
            c += __shfl_down_sync(0xffffu, c, o);
            l += __shfl_down_sync(0xffffu, l, o);
        }
        if (lane == 0) { snpos = n; g_np[b] = n; g_cp[b] = c; g_loc[b] = l; }
    }
    __syncthreads();

    // ---------------- Phase C: exact top-K via radix select on smem ------
    int K = 3 * snpos;
    if (K > NP) K = NP;

    unsigned t = 0u;
    for (int bit = 30; bit >= 0; --bit) {
        unsigned cand = t | (1u << bit);
        int c = 0;
        for (int p = tid; p < NP; p += TPB)
            if (__float_as_uint(sce[p]) >= cand) c++;
        #pragma unroll
        for (int o = 16; o > 0; o >>= 1) c += __shfl_down_sync(0xffffffffu, c, o);
        if (lane == 0 && c) atomicAdd(&sscnt[bit], c);
        __syncthreads();
        if (sscnt[bit] >= K) t = cand;
        // next pass uses a different counter slot -> no second sync needed
    }

    int    cgt = 0;
    double sg  = 0.0;
    for (int p = tid; p < NP; p += TPB) {
        unsigned v = __float_as_uint(sce[p]);
        if (v > t) { cgt++; sg += (double)__uint_as_float(v); }
    }
    #pragma unroll
    for (int o = 16; o > 0; o >>= 1) {
        cgt += __shfl_down_sync(0xffffffffu, cgt, o);
        sg  += __shfl_down_sync(0xffffffffu, sg, o);
    }
    __syncthreads();            // safe reuse of siw/sdw
    if (lane == 0) { siw[wid] = cgt; sdw[wid] = sg; }
    __syncthreads();
    if (tid == 0) {
        int c = 0; double sm = 0.0;
        #pragma unroll
        for (int w = 0; w < 16; w++) { c += siw[w]; sm += sdw[w]; }
        g_hard[b] = sm + (double)(K - c) * (double)__uint_as_float(t);
    }
}

// ---------------- finalize: reduce 128 per-image slots ----------------
__global__ void finalize_k(float* __restrict__ out) {
    int tid  = threadIdx.x;           // 128 threads
    int lane = tid & 31, wid = tid >> 5;
    double h = g_hard[tid] + g_cp[tid];
    double l = g_loc[tid];
    int    n = g_np[tid];
    #pragma unroll
    for (int o = 16; o > 0; o >>= 1) {
        h += __shfl_down_sync(0xffffffffu, h, o);
        l += __shfl_down_sync(0xffffffffu, l, o);
        n += __shfl_down_sync(0xffffffffu, n, o);
    }
    __shared__ double sh[4], sl[4];
    __shared__ int    sn[4];
    if (lane == 0) { sh[wid] = h; sl[wid] = l; sn[wid] = n; }
    __syncthreads();
    if (tid == 0) {
        double H = sh[0] + sh[1] + sh[2] + sh[3];
        double L = sl[0] + sl[1] + sl[2] + sl[3];
        double N = (double)(sn[0] + sn[1] + sn[2] + sn[3]);
        double loc  = ALPHA * (L / (N * 4.0));
        double conf = H / N;
        out[0] = (float)(conf + loc);
        out[1] = (float)loc;
        out[2] = (float)conf;
    }
}

extern "C" void kernel_launch(void* const* d_in, const int* in_sizes, int n_in,
                              void* d_out, int out_size) {
    const float* pred_loc = (const float*)d_in[0];
    const float* pred_cls = (const float*)d_in[1];
    const float* b_boxes  = (const float*)d_in[2];
    const int*   b_labels = (const int*)  d_in[3];
    const float* priors   = (const float*)d_in[4];
    float* out = (float*)d_out;

    cudaFuncSetAttribute(fused_k, cudaFuncAttributeMaxDynamicSharedMemorySize,
                         DSM_BYTES);
    fused_k<<<NB, TPB, DSM_BYTES>>>(pred_loc, pred_cls, b_boxes, b_labels, priors);
    finalize_k<<<1, NB>>>(out);
}

// round 13
// speedup vs baseline: 1.3372x; 1.0038x over previous
#include <cuda_runtime.h>
#include <math.h>
#include <stdint.h>

#define NP 8732
#define NC 21
#define NB 128
#define NO 32
#define THRESH 0.5f
#define ALPHA 10.0

// K1: IoU kernel decomposition
#define NCH 4                 // prior chunks per image (8732 = 4*2183)
#define CP  2183              // priors per chunk
#define K1_TPB 256
#define K1_PPT 9              // ceil(2183/256)

// K2: CE kernel decomposition (groups of 4 priors)
#define NG  2183              // total groups (8732/4)
#define GPC 546               // groups per chunk (ceil(2183/4))
#define K2_TPB 256
#define K2_GPT 3              // ceil(546/256)

// K3
#define K3_TPB 512
#define K3_VPT 18             // ceil(8732/512)

// -------- device scratch --------
__device__ unsigned long long g_obj[NB * NO];     // packed (iou_bits<<32)|~prior
__device__ unsigned long long g_pbest[NB * NP];   // packed (iou_bits<<32)|obj
__device__ float  g_ce[NB * NP];                  // CE of negatives (0 for pos)
__device__ int    g_np[NB];
__device__ double g_cp[NB];
__device__ double g_loc[NB];
__device__ double g_hard[NB];

// ---------------------------------------------------------
__global__ void init_k() {
    int t = blockIdx.x * blockDim.x + threadIdx.x;
    if (t < NB * NO) g_obj[t] = 0ULL;
    if (t < NB) { g_np[t] = 0; g_cp[t] = 0.0; g_loc[t] = 0.0; }
}

// ---------------------------------------------------------
// K1: per-chunk IoU pass. grid = (NCH, NB), 256 threads.
// Prior corners in registers; 8 object-group passes of pure FMA/ALU.
// ---------------------------------------------------------
__global__ __launch_bounds__(K1_TPB, 2)
void iou_k(const float* __restrict__ b_boxes,
           const float* __restrict__ priors) {
    const int chunk = blockIdx.x;
    const int b     = blockIdx.y;
    const int tid   = threadIdx.x;
    const int lane  = tid & 31;
    const int wid   = tid >> 5;       // 0..7
    const int base  = chunk * CP;

    __shared__ float sbx1[NO], sby1[NO], sbx2[NO], sby2[NO], sba[NO];
    __shared__ float swv[4][8];
    __shared__ int   swi[4][8];

    if (tid < NO) {
        const float* bb = b_boxes + ((size_t)b * NO + tid) * 4;
        float x1 = bb[0], y1 = bb[1], x2 = bb[2], y2 = bb[3];
        sbx1[tid] = x1; sby1[tid] = y1; sbx2[tid] = x2; sby2[tid] = y2;
        sba[tid]  = (x2 - x1) * (y2 - y1);
    }
    __syncthreads();

    // prior corners in registers (45 regs)
    float px1[K1_PPT], py1[K1_PPT], px2[K1_PPT], py2[K1_PPT], pa[K1_PPT];
    #pragma unroll
    for (int i = 0; i < K1_PPT; i++) {
        int p = tid + i * K1_TPB;
        if (p < CP) {
            float4 pc = reinterpret_cast<const float4*>(priors)[base + p];
            float hw = pc.z * 0.5f, hh = pc.w * 0.5f;
            px1[i] = pc.x - hw; py1[i] = pc.y - hh;
            px2[i] = pc.x + hw; py2[i] = pc.y + hh;
            pa[i]  = (px2[i] - px1[i]) * (py2[i] - py1[i]);
        }
    }

    float pbv[K1_PPT]; int pbm[K1_PPT];
    #pragma unroll
    for (int i = 0; i < K1_PPT; i++) { pbv[i] = -1.0f; pbm[i] = 0; }

    for (int g = 0; g < NO / 4; ++g) {
        float B1[4], B2[4], B3[4], B4[4], BA[4];
        #pragma unroll
        for (int j = 0; j < 4; j++) {
            int m = g * 4 + j;
            B1[j] = sbx1[m]; B2[j] = sby1[m];
            B3[j] = sbx2[m]; B4[j] = sby2[m]; BA[j] = sba[m];
        }
        float obv[4]; int obi[4];
        #pragma unroll
        for (int j = 0; j < 4; j++) { obv[j] = -1.0f; obi[j] = 0x7fffffff; }

        #pragma unroll
        for (int i = 0; i < K1_PPT; i++) {
            int p = tid + i * K1_TPB;
            if (p < CP) {
                #pragma unroll
                for (int j = 0; j < 4; j++) {
                    float ix1 = fmaxf(B1[j], px1[i]), iy1 = fmaxf(B2[j], py1[i]);
                    float ix2 = fminf(B3[j], px2[i]), iy2 = fminf(B4[j], py2[i]);
                    float iw  = fmaxf(ix2 - ix1, 0.0f);
                    float ih  = fmaxf(iy2 - iy1, 0.0f);
                    float inter = iw * ih;
                    float uni   = (BA[j] + pa[i]) - inter;
                    float iou   = __fdividef(inter, uni);
                    if (iou > pbv[i]) { pbv[i] = iou; pbm[i] = g * 4 + j; }
                    if (iou > obv[j]) { obv[j] = iou; obi[j] = base + p; }
                }
            }
        }
        // per-object block argmax (min index ties), then one atomicMax each
        #pragma unroll
        for (int j = 0; j < 4; j++) {
            float v = obv[j]; int ix = obi[j];
            #pragma unroll
            for (int o = 16; o > 0; o >>= 1) {
                float v2 = __shfl_down_sync(0xffffffffu, v, o);
                int   i2 = __shfl_down_sync(0xffffffffu, ix, o);
                if (v2 > v || (v2 == v && i2 < ix)) { v = v2; ix = i2; }
            }
            if (lane == 0) { swv[j][wid] = v; swi[j][wid] = ix; }
        }
        __syncthreads();
        if (tid < 32) {
            int j = lane >> 3, w = lane & 7;
            float v = swv[j][w]; int ix = swi[j][w];
            #pragma unroll
            for (int o = 4; o > 0; o >>= 1) {
                float v2 = __shfl_down_sync(0xffffffffu, v, o);
                int   i2 = __shfl_down_sync(0xffffffffu, ix, o);
                if (v2 > v || (v2 == v && i2 < ix)) { v = v2; ix = i2; }
            }
            if (w == 0) {
                unsigned long long pk =
                    ((unsigned long long)__float_as_uint(v) << 32) | (unsigned)(~ix);
                atomicMax(&g_obj[b * NO + g * 4 + j], pk);
            }
        }
        __syncthreads();
    }

    // store per-prior best (pre-override), packed
    #pragma unroll
    for (int i = 0; i < K1_PPT; i++) {
        int p = tid + i * K1_TPB;
        if (p < CP)
            g_pbest[(size_t)b * NP + base + p] =
                ((unsigned long long)__float_as_uint(pbv[i]) << 32) | (unsigned)pbm[i];
    }
}

// ---------------------------------------------------------
// K2: match fix-up + CE + loc. grid = (NCH, NB), 256 threads.
// ---------------------------------------------------------
__global__ __launch_bounds__(K2_TPB, 4)
void ce_k(const float* __restrict__ pred_loc,
          const float* __restrict__ pred_cls,
          const float* __restrict__ b_boxes,
          const int*   __restrict__ b_labels,
          const float* __restrict__ priors) {
    const int chunk = blockIdx.x;
    const int b     = blockIdx.y;
    const int tid   = threadIdx.x;
    const int lane  = tid & 31;
    const int wid   = tid >> 5;       // 0..7
    const int gbase = chunk * GPC;
    const int pbase = gbase * 4;
    const int pcount = min(NP - pbase, GPC * 4);

    __shared__ float sbx1[NO], sby1[NO], sbx2[NO], sby2[NO];
    __shared__ int   slab[NO];
    __shared__ unsigned char sov[GPC * 4];
    __shared__ int    siw[8];
    __shared__ double sdw[8], sdw2[8];

    if (tid < NO) {
        const float* bb = b_boxes + ((size_t)b * NO + tid) * 4;
        sbx1[tid] = bb[0]; sby1[tid] = bb[1]; sbx2[tid] = bb[2]; sby2[tid] = bb[3];
        slab[tid] = b_labels[b * NO + tid];
    }
    for (int i = tid; i < pcount; i += K2_TPB) sov[i] = 255;
    __syncthreads();
    if (tid == 0) {
        for (int m = NO - 1; m >= 0; --m) {     // descending: min m wins
            unsigned long long v = g_obj[b * NO + m];
            int p = (int)(~(unsigned)(v & 0xffffffffu));
            int r = p - pbase;
            if (r >= 0 && r < pcount) sov[r] = (unsigned char)m;
        }
    }
    __syncthreads();

    int    npl  = 0;
    double cpl  = 0.0;
    double locl = 0.0;

    #pragma unroll
    for (int it = 0; it < K2_GPT; it++) {
        int gl  = tid + it * K2_TPB;
        int grp = gbase + gl;
        if (gl < GPC && grp < NG) {
            int  cls[4]; bool pos[4]; int bm[4];
            #pragma unroll
            for (int j = 0; j < 4; j++) {
                int p = grp * 4 + j;
                unsigned long long pk = g_pbest[(size_t)b * NP + p];
                float bv = __uint_as_float((unsigned)(pk >> 32));
                int   m  = (int)(pk & 0xffffffffu);
                int ov = sov[p - pbase];
                if (ov != 255) {
                    if (bv < 1.0f || (bv == 1.0f && ov < m)) { bv = 1.0f; m = ov; }
                }
                pos[j] = (bv >= THRESH);
                bm[j]  = m;
                cls[j] = pos[j] ? slab[m] : 0;
            }

            const float4* basep = reinterpret_cast<const float4*>(
                pred_cls + ((size_t)b * NP + (size_t)grp * 4) * NC);
            float se[4] = {0.f, 0.f, 0.f, 0.f};
            float lc[4] = {0.f, 0.f, 0.f, 0.f};
            #pragma unroll
            for (int k = 0; k < NC; k++) {       // 21 float4 = 84 logits
                float4 v = basep[k];
                {   int e = 4 * k + 0, r = e / NC, c = e % NC;
                    se[r] += __expf(v.x); if (c == cls[r]) lc[r] = v.x; }
                {   int e = 4 * k + 1, r = e / NC, c = e % NC;
                    se[r] += __expf(v.y); if (c == cls[r]) lc[r] = v.y; }
                {   int e = 4 * k + 2, r = e / NC, c = e % NC;
                    se[r] += __expf(v.z); if (c == cls[r]) lc[r] = v.z; }
                {   int e = 4 * k + 3, r = e / NC, c = e % NC;
                    se[r] += __expf(v.w); if (c == cls[r]) lc[r] = v.w; }
            }

            float cearr[4];
            #pragma unroll
            for (int j = 0; j < 4; j++) {
                int p = grp * 4 + j;
                float ce = __logf(se[j]) - lc[j];
                if (pos[j]) {
                    cearr[j] = 0.0f;
                    npl++;
                    cpl += (double)ce;
                    float4 pc = reinterpret_cast<const float4*>(priors)[p];
                    int m = bm[j];
                    float x1 = sbx1[m], y1 = sby1[m], x2 = sbx2[m], y2 = sby2[m];
                    float cx = (x1 + x2) * 0.5f, cy = (y1 + y2) * 0.5f;
                    float bw = x2 - x1, bh = y2 - y1;
                    float gx = (cx - pc.x) / (pc.z / 10.0f);
                    float gy = (cy - pc.y) / (pc.w / 10.0f);
                    float gw = __logf(bw / pc.z) * 5.0f;
                    float gh = __logf(bh / pc.w) * 5.0f;
                    float4 pl = reinterpret_cast<const float4*>(pred_loc)[(size_t)b * NP + p];
                    locl += (double)(fabsf(pl.x - gx) + fabsf(pl.y - gy) +
                                     fabsf(pl.z - gw) + fabsf(pl.w - gh));
                } else {
                    cearr[j] = fmaxf(ce, 0.0f);
                }
            }
            *reinterpret_cast<float4*>(g_ce + (size_t)b * NP + (size_t)grp * 4) =
                make_float4(cearr[0], cearr[1], cearr[2], cearr[3]);
        }
    }

    // block reduce + one atomic per quantity
    #pragma unroll
    for (int o = 16; o > 0; o >>= 1) {
        npl  += __shfl_down_sync(0xffffffffu, npl, o);
        cpl  += __shfl_down_sync(0xffffffffu, cpl, o);
        locl += __shfl_down_sync(0xffffffffu, locl, o);
    }
    if (lane == 0) { siw[wid] = npl; sdw[wid] = cpl; sdw2[wid] = locl; }
    __syncthreads();
    if (tid == 0) {
        int n = 0; double c = 0.0, l = 0.0;
        #pragma unroll
        for (int w = 0; w < 8; w++) { n += siw[w]; c += sdw[w]; l += sdw2[w]; }
        if (n) atomicAdd(&g_np[b], n);
        atomicAdd(&g_cp[b], c);
        atomicAdd(&g_loc[b], l);
    }
}

// ---------------------------------------------------------
// K3: per-image exact top-K sum, register radix select. grid=NB, 512 thr.
// ---------------------------------------------------------
__global__ __launch_bounds__(K3_TPB)
void hard_k() {
    const int b    = blockIdx.x;
    const int tid  = threadIdx.x;
    const int lane = tid & 31;
    const int wid  = tid >> 5;      // 0..15

    __shared__ int    sscnt[32];
    __shared__ int    siw[16];
    __shared__ double sdw[16];

    unsigned v[K3_VPT];
    #pragma unroll
    for (int i = 0; i < K3_VPT; i++) {
        int p = tid + i * K3_TPB;
        v[i] = (p < NP) ? __float_as_uint(g_ce[(size_t)b * NP + p]) : 0u;
    }
    if (tid < 32) sscnt[tid] = 0;
    int K = 3 * g_np[b];
    if (K > NP) K = NP;
    __syncthreads();

    unsigned t = 0u;
    for (int bit = 30; bit >= 0; --bit) {
        unsigned cand = t | (1u << bit);
        int c = 0;
        #pragma unroll
        for (int i = 0; i < K3_VPT; i++)
            if (v[i] >= cand) c++;
        #pragma unroll
        for (int o = 16; o > 0; o >>= 1) c += __shfl_down_sync(0xffffffffu, c, o);
        if (lane == 0 && c) atomicAdd(&sscnt[bit], c);
        __syncthreads();
        if (sscnt[bit] >= K) t = cand;
        // next pass uses a different counter slot -> single sync per pass
    }

    int    cgt = 0;
    double sg  = 0.0;
    #pragma unroll
    for (int i = 0; i < K3_VPT; i++) {
        if (v[i] > t) { cgt++; sg += (double)__uint_as_float(v[i]); }
    }
    #pragma unroll
    for (int o = 16; o > 0; o >>= 1) {
        cgt += __shfl_down_sync(0xffffffffu, cgt, o);
        sg  += __shfl_down_sync(0xffffffffu, sg, o);
    }
    if (lane == 0) { siw[wid] = cgt; sdw[wid] = sg; }
    __syncthreads();
    if (tid == 0) {
        int c = 0; double sm = 0.0;
        #pragma unroll
        for (int w = 0; w < 16; w++) { c += siw[w]; sm += sdw[w]; }
        g_hard[b] = sm + (double)(K - c) * (double)__uint_as_float(t);
    }
}

// ---------------- finalize: reduce 128 per-image slots ----------------
__global__ void finalize_k(float* __restrict__ out) {
    int tid  = threadIdx.x;           // 128 threads
    int lane = tid & 31, wid = tid >> 5;
    double h = g_hard[tid] + g_cp[tid];
    double l = g_loc[tid];
    int    n = g_np[tid];
    #pragma unroll
    for (int o = 16; o > 0; o >>= 1) {
        h += __shfl_down_sync(0xffffffffu, h, o);
        l += __shfl_down_sync(0xffffffffu, l, o);
        n += __shfl_down_sync(0xffffffffu, n, o);
    }
    __shared__ double sh[4], sl[4];
    __shared__ int    sn[4];
    if (lane == 0) { sh[wid] = h; sl[wid] = l; sn[wid] = n; }
    __syncthreads();
    if (tid == 0) {
        double H = sh[0] + sh[1] + sh[2] + sh[3];
        double L = sl[0] + sl[1] + sl[2] + sl[3];
        double N = (double)(sn[0] + sn[1] + sn[2] + sn[3]);
        double loc  = ALPHA * (L / (N * 4.0));
        double conf = H / N;
        out[0] = (float)(conf + loc);
        out[1] = (float)loc;
        out[2] = (float)conf;
    }
}

extern "C" void kernel_launch(void* const* d_in, const int* in_sizes, int n_in,
                              void* d_out, int out_size) {
    const float* pred_loc = (const float*)d_in[0];
    const float* pred_cls = (const float*)d_in[1];
    const float* b_boxes  = (const float*)d_in[2];
    const int*   b_labels = (const int*)  d_in[3];
    const float* priors   = (const float*)d_in[4];
    float* out = (float*)d_out;

    init_k<<<(NB * NO + 255) / 256, 256>>>();
    iou_k<<<dim3(NCH, NB), K1_TPB>>>(b_boxes, priors);
    ce_k<<<dim3(NCH, NB), K2_TPB>>>(pred_loc, pred_cls, b_boxes, b_labels, priors);
    hard_k<<<NB, K3_TPB>>>();
    finalize_k<<<1, NB>>>(out);
}